// round 1
// baseline (speedup 1.0000x reference)
#include <cuda_runtime.h>
#include <cuda_bf16.h>

#define NN      50000
#define EE      800000
#define INDIM   256
#define TD      16
#define HID     256
#define NUMT    50
#define NOUT    512   // z (256) + r (256)

// ---------------- scratch (device globals; no runtime alloc) ----------------
__device__ int   g_cnt[NN];
__device__ int   g_off[NN + 1];
__device__ int   g_cur[NN];
__device__ int   g_csr[EE];
__device__ float g_z[(size_t)NN * HID];   // x @ W1_l^T (+ time-l term)
__device__ float g_r[(size_t)NN * HID];   // x @ W1_r^T (+ time-r term + b1)
__device__ float g_teL[NUMT * HID];
__device__ float g_teR[NUMT * HID];
__device__ float g_sl[NN];
__device__ float g_sr[NN];

// ---------------- CSR build ----------------
__global__ void k_zero(int n) {
    int i = blockIdx.x * blockDim.x + threadIdx.x;
    if (i < n) g_cnt[i] = 0;
}

__global__ void k_count(const int* __restrict__ edge, int E) {
    int e = blockIdx.x * blockDim.x + threadIdx.x;
    if (e < E) atomicAdd(&g_cnt[edge[E + e]], 1);
}

// single-block exclusive scan over g_cnt -> g_off, g_cur
__global__ void k_scan(int n) {
    const int tid = threadIdx.x;
    const int lane = tid & 31, w = tid >> 5;
    __shared__ int ws[32];
    __shared__ int sbase;
    if (tid == 0) sbase = 0;
    __syncthreads();
    for (int start = 0; start < n; start += 1024) {
        int idx = start + tid;
        int v = (idx < n) ? g_cnt[idx] : 0;
        int sv = v;
        #pragma unroll
        for (int o = 1; o < 32; o <<= 1) {
            int t = __shfl_up_sync(0xffffffffu, sv, o);
            if (lane >= o) sv += t;
        }
        if (lane == 31) ws[w] = sv;
        __syncthreads();
        if (w == 0) {
            int t = ws[lane];
            #pragma unroll
            for (int o = 1; o < 32; o <<= 1) {
                int u = __shfl_up_sync(0xffffffffu, t, o);
                if (lane >= o) t += u;
            }
            ws[lane] = t;
        }
        __syncthreads();
        int excl = sbase + (w > 0 ? ws[w - 1] : 0) + sv - v;
        if (idx < n) { g_off[idx] = excl; g_cur[idx] = excl; }
        __syncthreads();                 // all reads of sbase/ws done
        if (tid == 0) sbase += ws[31];
        __syncthreads();
    }
    if (tid == 0) g_off[n] = sbase;
}

__global__ void k_fill(const int* __restrict__ edge, int E) {
    int e = blockIdx.x * blockDim.x + threadIdx.x;
    if (e < E) {
        int s = edge[e];
        int d = edge[E + e];
        int p = atomicAdd(&g_cur[d], 1);
        g_csr[p] = s;
    }
}

// ---------------- time-embedding projection tables ----------------
// teL[t][h] = sum_d te[t][d] * W1_l[h][256+d]
// teR[t][h] = sum_d te[t][d] * W1_r[h][256+d] + b1[h]
__global__ void k_teproj(const float* __restrict__ te,
                         const float* __restrict__ W1l,
                         const float* __restrict__ W1r,
                         const float* __restrict__ b1) {
    int t = blockIdx.x;
    int h = threadIdx.x;
    float sl = 0.f, sr = 0.f;
    #pragma unroll
    for (int d = 0; d < TD; ++d) {
        float tv = te[t * TD + d];
        sl += tv * W1l[h * (INDIM + TD) + INDIM + d];
        sr += tv * W1r[h * (INDIM + TD) + INDIM + d];
    }
    g_teL[t * HID + h] = sl;
    g_teR[t * HID + h] = sr + b1[h];
}

// ---------------- fused GEMM: [z | r] = X @ [W1_l_x ; W1_r_x]^T + time terms ----------------
#define BM 128
#define BN 128
#define BK 8

__global__ __launch_bounds__(256) void k_gemm(const float* __restrict__ X,
                       const float* __restrict__ W1l,
                       const float* __restrict__ W1r,
                       const int*   __restrict__ ts,
                       int M) {
    __shared__ __align__(16) float As[BK][BM];
    __shared__ __align__(16) float Bs[BK][BN];

    const int n0 = blockIdx.x * BN;          // 0,128,256,384
    const int m0 = blockIdx.y * BM;
    const int tid = threadIdx.x;
    const int tx = tid & 15, ty = tid >> 4;

    const bool isZ = (n0 < 256);
    const float* Wp = isZ ? W1l : W1r;
    const int cbase = isZ ? n0 : (n0 - 256);

    const int arow = tid >> 1, akq = (tid & 1) * 4;  // A: 128 rows x 8 k = 256 float4
    const int brow = tid >> 1, bkq = (tid & 1) * 4;  // B: 128 cols x 8 k

    float acc[8][8];
    #pragma unroll
    for (int i = 0; i < 8; ++i)
        #pragma unroll
        for (int j = 0; j < 8; ++j) acc[i][j] = 0.f;

    auto loadA = [&](int k0) -> float4 {
        int m = m0 + arow;
        if (m < M) return *reinterpret_cast<const float4*>(X + (size_t)m * INDIM + k0 + akq);
        return make_float4(0.f, 0.f, 0.f, 0.f);
    };
    auto loadB = [&](int k0) -> float4 {
        return *reinterpret_cast<const float4*>(Wp + (size_t)(cbase + brow) * (INDIM + TD) + k0 + bkq);
    };

    float4 aF = loadA(0);
    float4 bF = loadB(0);

    for (int k0 = 0; k0 < INDIM; k0 += BK) {
        As[akq + 0][arow] = aF.x; As[akq + 1][arow] = aF.y;
        As[akq + 2][arow] = aF.z; As[akq + 3][arow] = aF.w;
        Bs[bkq + 0][brow] = bF.x; Bs[bkq + 1][brow] = bF.y;
        Bs[bkq + 2][brow] = bF.z; Bs[bkq + 3][brow] = bF.w;
        __syncthreads();

        if (k0 + BK < INDIM) { aF = loadA(k0 + BK); bF = loadB(k0 + BK); }

        #pragma unroll
        for (int kk = 0; kk < BK; ++kk) {
            float4 A0 = *reinterpret_cast<const float4*>(&As[kk][ty * 4]);
            float4 A1 = *reinterpret_cast<const float4*>(&As[kk][64 + ty * 4]);
            float4 B0 = *reinterpret_cast<const float4*>(&Bs[kk][tx * 4]);
            float4 B1 = *reinterpret_cast<const float4*>(&Bs[kk][64 + tx * 4]);
            float av[8] = {A0.x, A0.y, A0.z, A0.w, A1.x, A1.y, A1.z, A1.w};
            float bv[8] = {B0.x, B0.y, B0.z, B0.w, B1.x, B1.y, B1.z, B1.w};
            #pragma unroll
            for (int i = 0; i < 8; ++i)
                #pragma unroll
                for (int j = 0; j < 8; ++j)
                    acc[i][j] += av[i] * bv[j];
        }
        __syncthreads();
    }

    // epilogue: add time table (+bias folded into teR), write to g_z / g_r
    #pragma unroll
    for (int i = 0; i < 8; ++i) {
        int m = m0 + ((i < 4) ? (ty * 4 + i) : (64 + ty * 4 + (i - 4)));
        if (m >= M) continue;
        int t = ts[m];
        const float* tab = isZ ? (g_teL + t * HID) : (g_teR + t * HID);
        float* outp = isZ ? g_z : g_r;
        #pragma unroll
        for (int j = 0; j < 8; ++j) {
            int c = cbase + ((j < 4) ? (tx * 4 + j) : (64 + tx * 4 + (j - 4)));
            outp[(size_t)m * HID + c] = acc[i][j] + tab[c];
        }
    }
}

// ---------------- layer-1 aggregation + relu + head dot products ----------------
// warp per node: h1 = relu(mean_z_neighbors + r); sl = h1.Wh_l; sr = h1.Wh_r
__global__ __launch_bounds__(256) void k_agg(const float* __restrict__ Whl,
                                             const float* __restrict__ Whr,
                                             int n) {
    const int warp = threadIdx.x >> 5, lane = threadIdx.x & 31;
    const int node = blockIdx.x * 8 + warp;
    if (node >= n) return;

    const int beg = g_off[node], end = g_off[node + 1];
    const int deg = end - beg;

    float4 a0 = make_float4(0.f, 0.f, 0.f, 0.f);
    float4 a1 = make_float4(0.f, 0.f, 0.f, 0.f);
    const float4* Z = reinterpret_cast<const float4*>(g_z);

    int e = beg;
    for (; e + 1 < end; e += 2) {
        int j0 = g_csr[e], j1 = g_csr[e + 1];
        const float4* p0 = Z + (size_t)j0 * 64;
        const float4* p1 = Z + (size_t)j1 * 64;
        float4 x0 = p0[lane],       y0 = p0[32 + lane];
        float4 x1 = p1[lane],       y1 = p1[32 + lane];
        a0.x += x0.x + x1.x; a0.y += x0.y + x1.y; a0.z += x0.z + x1.z; a0.w += x0.w + x1.w;
        a1.x += y0.x + y1.x; a1.y += y0.y + y1.y; a1.z += y0.z + y1.z; a1.w += y0.w + y1.w;
    }
    if (e < end) {
        int j0 = g_csr[e];
        const float4* p0 = Z + (size_t)j0 * 64;
        float4 x0 = p0[lane], y0 = p0[32 + lane];
        a0.x += x0.x; a0.y += x0.y; a0.z += x0.z; a0.w += x0.w;
        a1.x += y0.x; a1.y += y0.y; a1.z += y0.z; a1.w += y0.w;
    }

    const float inv = 1.0f / (float)max(deg, 1);
    const float4* R = reinterpret_cast<const float4*>(g_r);
    float4 r0 = R[(size_t)node * 64 + lane];
    float4 r1 = R[(size_t)node * 64 + 32 + lane];

    float4 h0, h1v;
    h0.x = fmaxf(a0.x * inv + r0.x, 0.f);
    h0.y = fmaxf(a0.y * inv + r0.y, 0.f);
    h0.z = fmaxf(a0.z * inv + r0.z, 0.f);
    h0.w = fmaxf(a0.w * inv + r0.w, 0.f);
    h1v.x = fmaxf(a1.x * inv + r1.x, 0.f);
    h1v.y = fmaxf(a1.y * inv + r1.y, 0.f);
    h1v.z = fmaxf(a1.z * inv + r1.z, 0.f);
    h1v.w = fmaxf(a1.w * inv + r1.w, 0.f);

    const float4* wl4 = reinterpret_cast<const float4*>(Whl);
    const float4* wr4 = reinterpret_cast<const float4*>(Whr);
    float4 wl0 = __ldg(&wl4[lane]), wl1 = __ldg(&wl4[32 + lane]);
    float4 wr0 = __ldg(&wr4[lane]), wr1 = __ldg(&wr4[32 + lane]);

    float sl = h0.x * wl0.x + h0.y * wl0.y + h0.z * wl0.z + h0.w * wl0.w
             + h1v.x * wl1.x + h1v.y * wl1.y + h1v.z * wl1.z + h1v.w * wl1.w;
    float sr = h0.x * wr0.x + h0.y * wr0.y + h0.z * wr0.z + h0.w * wr0.w
             + h1v.x * wr1.x + h1v.y * wr1.y + h1v.z * wr1.z + h1v.w * wr1.w;

    #pragma unroll
    for (int o = 16; o > 0; o >>= 1) {
        sl += __shfl_xor_sync(0xffffffffu, sl, o);
        sr += __shfl_xor_sync(0xffffffffu, sr, o);
    }
    if (lane == 0) { g_sl[node] = sl; g_sr[node] = sr; }
}

// ---------------- layer-2 scalar aggregation ----------------
__global__ void k_out(const float* __restrict__ bh, float* __restrict__ out, int n) {
    int node = blockIdx.x * blockDim.x + threadIdx.x;
    if (node >= n) return;
    int beg = g_off[node], end = g_off[node + 1];
    float s = 0.f;
    for (int e = beg; e < end; ++e) s += g_sl[g_csr[e]];
    out[node] = s / (float)max(end - beg, 1) + bh[0] + g_sr[node];
}

// ---------------- launch ----------------
extern "C" void kernel_launch(void* const* d_in, const int* in_sizes, int n_in,
                              void* d_out, int out_size) {
    const float* x    = (const float*)d_in[0];
    const int*   edge = (const int*)  d_in[1];
    const int*   ts   = (const int*)  d_in[2];
    const float* te   = (const float*)d_in[3];
    const float* W1l  = (const float*)d_in[4];
    const float* b1   = (const float*)d_in[5];
    const float* W1r  = (const float*)d_in[6];
    const float* Whl  = (const float*)d_in[7];
    const float* bh   = (const float*)d_in[8];
    const float* Whr  = (const float*)d_in[9];
    float* out = (float*)d_out;

    const int N = in_sizes[0] / INDIM;
    const int E = in_sizes[1] / 2;

    k_zero <<<(N + 255) / 256, 256>>>(N);
    k_count<<<(E + 255) / 256, 256>>>(edge, E);
    k_scan <<<1, 1024>>>(N);
    k_fill <<<(E + 255) / 256, 256>>>(edge, E);
    k_teproj<<<NUMT, HID>>>(te, W1l, W1r, b1);
    dim3 gg(NOUT / BN, (N + BM - 1) / BM);
    k_gemm<<<gg, 256>>>(x, W1l, W1r, ts, N);
    k_agg <<<(N + 7) / 8, 256>>>(Whl, Whr, N);
    k_out <<<(N + 255) / 256, 256>>>(bh, out, N);
}

// round 2
// speedup vs baseline: 2.0532x; 2.0532x over previous
#include <cuda_runtime.h>
#include <cuda_bf16.h>
#include <cstdint>

#define NN      50000
#define EE      800000
#define INDIM   256
#define TD      16
#define HID     256
#define NUMT    50
#define AUG     (INDIM + TD)

// ---------------- scratch (device globals; no runtime alloc) ----------------
__device__ int   g_cnt[NN];
__device__ int   g_off[NN + 1];
__device__ int   g_cur[NN];
__device__ int   g_bsum[128];
__device__ int   g_bpre[128];
__device__ int   g_csr[EE];
__device__ float g_z[(size_t)NN * HID];   // x @ W1_l^T (+ time-l term)
__device__ float g_r[(size_t)NN * HID];   // x @ W1_r^T (+ time-r term + b1)
__device__ float g_teL[NUMT * HID];
__device__ float g_teR[NUMT * HID];
__device__ float g_sl[NN];
__device__ float g_sr[NN];

// ---------------- CSR build ----------------
__global__ void k_zero(int n) {
    int i = blockIdx.x * blockDim.x + threadIdx.x;
    if (i < n) g_cnt[i] = 0;
}

__global__ void k_count(const int* __restrict__ edge, int E) {
    int e = blockIdx.x * blockDim.x + threadIdx.x;
    if (e < E) atomicAdd(&g_cnt[edge[E + e]], 1);
}

#define SCAN_B 512
// phase 1: per-block exclusive scan of g_cnt -> g_off (local), block totals -> g_bsum
__global__ __launch_bounds__(SCAN_B) void k_scan1(int n) {
    __shared__ int ws[16];
    const int tid = threadIdx.x, lane = tid & 31, w = tid >> 5;
    const int idx = blockIdx.x * SCAN_B + tid;
    int v = (idx < n) ? g_cnt[idx] : 0;
    int sv = v;
    #pragma unroll
    for (int o = 1; o < 32; o <<= 1) {
        int t = __shfl_up_sync(0xffffffffu, sv, o);
        if (lane >= o) sv += t;
    }
    if (lane == 31) ws[w] = sv;
    __syncthreads();
    if (w == 0) {
        int t = (lane < 16) ? ws[lane] : 0;
        #pragma unroll
        for (int o = 1; o < 16; o <<= 1) {
            int u = __shfl_up_sync(0xffffffffu, t, o);
            if (lane >= o) t += u;
        }
        if (lane < 16) ws[lane] = t;
    }
    __syncthreads();
    int excl = (w ? ws[w - 1] : 0) + sv - v;
    if (idx < n) g_off[idx] = excl;
    if (tid == 0) g_bsum[blockIdx.x] = ws[15];
}

// phase 2: single block scans block totals -> g_bpre; writes g_off[n]
__global__ void k_scan2(int nb, int n) {
    __shared__ int wsum[5];
    const int tid = threadIdx.x, lane = tid & 31, w = tid >> 5;
    int v = (tid < nb) ? g_bsum[tid] : 0;
    int sv = v;
    #pragma unroll
    for (int o = 1; o < 32; o <<= 1) {
        int t = __shfl_up_sync(0xffffffffu, sv, o);
        if (lane >= o) sv += t;
    }
    if (lane == 31) wsum[w] = sv;
    __syncthreads();
    if (tid == 0) {
        int a = 0;
        #pragma unroll
        for (int i = 0; i < 4; i++) { int t = wsum[i]; wsum[i] = a; a += t; }
        wsum[4] = a;
    }
    __syncthreads();
    int excl = wsum[w] + sv - v;
    if (tid < nb) g_bpre[tid] = excl;
    if (tid == 0) g_off[n] = wsum[4];
}

// phase 3: add block prefixes, init g_cur
__global__ __launch_bounds__(SCAN_B) void k_scan3(int n) {
    int idx = blockIdx.x * SCAN_B + threadIdx.x;
    if (idx < n) {
        int o = g_off[idx] + g_bpre[blockIdx.x];
        g_off[idx] = o;
        g_cur[idx] = o;
    }
}

__global__ void k_fill(const int* __restrict__ edge, int E) {
    int e = blockIdx.x * blockDim.x + threadIdx.x;
    if (e < E) {
        int s = edge[e];
        int d = edge[E + e];
        int p = atomicAdd(&g_cur[d], 1);
        g_csr[p] = s;
    }
}

// ---------------- time-embedding projection tables ----------------
__global__ void k_teproj(const float* __restrict__ te,
                         const float* __restrict__ W1l,
                         const float* __restrict__ W1r,
                         const float* __restrict__ b1) {
    int t = blockIdx.x;
    int h = threadIdx.x;
    float sl = 0.f, sr = 0.f;
    #pragma unroll
    for (int d = 0; d < TD; ++d) {
        float tv = te[t * TD + d];
        sl += tv * W1l[h * AUG + INDIM + d];
        sr += tv * W1r[h * AUG + INDIM + d];
    }
    g_teL[t * HID + h] = sl;
    g_teR[t * HID + h] = sr + b1[h];
}

// ---------------- tf32 tensor-core GEMM ----------------
#define BM 128
#define BN 128
#define BK 32
#define LDAS 36                 // BK + 4 pad -> conflict-free fragment LDS
#define ASZ (BM * LDAS)         // floats per tile per stage

__device__ __forceinline__ void cp16(float* dst, const float* src, bool valid) {
    uint32_t d = (uint32_t)__cvta_generic_to_shared(dst);
    int sz = valid ? 16 : 0;
    asm volatile("cp.async.cg.shared.global [%0], [%1], 16, %2;\n"
                 :: "r"(d), "l"(src), "r"(sz));
}

__device__ __forceinline__ void mma_tf32(float4& d, const uint32_t a[4], const uint32_t b[2]) {
    asm volatile(
        "mma.sync.aligned.m16n8k8.row.col.f32.tf32.tf32.f32 "
        "{%0,%1,%2,%3}, {%4,%5,%6,%7}, {%8,%9}, {%0,%1,%2,%3};\n"
        : "+f"(d.x), "+f"(d.y), "+f"(d.z), "+f"(d.w)
        : "r"(a[0]), "r"(a[1]), "r"(a[2]), "r"(a[3]), "r"(b[0]), "r"(b[1]));
}

__device__ __forceinline__ void load_tile(float* As, float* Bs,
                                          const float* __restrict__ X,
                                          const float* __restrict__ Wp,
                                          int m0, int cbase, int M, int kb, int tid) {
    #pragma unroll
    for (int i = 0; i < 4; i++) {
        int c = tid + 256 * i;
        int row = c >> 3, col = (c & 7) * 4;
        int m = m0 + row;
        bool va = m < M;
        const float* sa = X + (size_t)(va ? m : 0) * INDIM + kb + col;
        cp16(As + row * LDAS + col, sa, va);
        const float* sb = Wp + (size_t)(cbase + row) * AUG + kb + col;
        cp16(Bs + row * LDAS + col, sb, true);
    }
}

__global__ __launch_bounds__(256) void k_gemm(const float* __restrict__ X,
                                              const float* __restrict__ W1l,
                                              const float* __restrict__ W1r,
                                              const int* __restrict__ ts,
                                              int M) {
    extern __shared__ float sm[];
    float* As  = sm;                 // [2][BM][LDAS]
    float* Bsm = sm + 2 * ASZ;       // [2][BN][LDAS]

    const int tid = threadIdx.x;
    const int n0 = blockIdx.x * BN;          // 0,128,256,384
    const int m0 = blockIdx.y * BM;
    const bool isZ = (n0 < 256);
    const float* Wp = isZ ? W1l : W1r;
    const int cbase = isZ ? n0 : (n0 - 256);

    const int warp = tid >> 5, lane = tid & 31;
    const int wm = warp >> 2, wn = warp & 3;   // warp grid 2 (m) x 4 (n)
    const int g = lane >> 2, tig = lane & 3;

    float4 acc[4][4];
    #pragma unroll
    for (int i = 0; i < 4; i++)
        #pragma unroll
        for (int j = 0; j < 4; j++) acc[i][j] = make_float4(0.f, 0.f, 0.f, 0.f);

    load_tile(As, Bsm, X, Wp, m0, cbase, M, 0, tid);
    asm volatile("cp.async.commit_group;\n");
    load_tile(As + ASZ, Bsm + ASZ, X, Wp, m0, cbase, M, BK, tid);
    asm volatile("cp.async.commit_group;\n");
    asm volatile("cp.async.wait_group 1;\n");
    __syncthreads();

    #pragma unroll 1
    for (int ks = 0; ks < INDIM / BK; ks++) {
        const int buf = ks & 1;
        const float* Ab = As + buf * ASZ;
        const float* Bb = Bsm + buf * ASZ;

        #pragma unroll
        for (int kk = 0; kk < 4; kk++) {
            uint32_t af[4][4], bf[4][2];
            const float* Ap = Ab + (wm * 64 + g) * LDAS + kk * 8 + tig;
            #pragma unroll
            for (int mt = 0; mt < 4; mt++) {
                af[mt][0] = __float_as_uint(Ap[(mt * 16)     * LDAS]);
                af[mt][1] = __float_as_uint(Ap[(mt * 16 + 8) * LDAS]);
                af[mt][2] = __float_as_uint(Ap[(mt * 16)     * LDAS + 4]);
                af[mt][3] = __float_as_uint(Ap[(mt * 16 + 8) * LDAS + 4]);
            }
            const float* Bp = Bb + (wn * 32 + g) * LDAS + kk * 8 + tig;
            #pragma unroll
            for (int nt = 0; nt < 4; nt++) {
                bf[nt][0] = __float_as_uint(Bp[(nt * 8) * LDAS]);
                bf[nt][1] = __float_as_uint(Bp[(nt * 8) * LDAS + 4]);
            }
            #pragma unroll
            for (int mt = 0; mt < 4; mt++)
                #pragma unroll
                for (int nt = 0; nt < 4; nt++)
                    mma_tf32(acc[mt][nt], af[mt], bf[nt]);
        }
        __syncthreads();
        if (ks + 2 < INDIM / BK) {
            load_tile(As + buf * ASZ, Bsm + buf * ASZ, X, Wp, m0, cbase, M, (ks + 2) * BK, tid);
            asm volatile("cp.async.commit_group;\n");
            asm volatile("cp.async.wait_group 1;\n");
        } else {
            asm volatile("cp.async.wait_group 0;\n");
        }
        __syncthreads();
    }

    // epilogue: add time tables (+bias folded into teR), write z / r
    float* outp = isZ ? g_z : g_r;
    const float* tabB = isZ ? g_teL : g_teR;
    #pragma unroll
    for (int mt = 0; mt < 4; mt++) {
        int mtp = m0 + wm * 64 + mt * 16 + g;
        int mbt = mtp + 8;
        int t0 = (mtp < M) ? ts[mtp] : 0;
        int t1 = (mbt < M) ? ts[mbt] : 0;
        const float* tb0 = tabB + t0 * HID;
        const float* tb1 = tabB + t1 * HID;
        #pragma unroll
        for (int nt = 0; nt < 4; nt++) {
            int c = cbase + wn * 32 + nt * 8 + tig * 2;
            if (mtp < M) {
                float2 v; v.x = acc[mt][nt].x + tb0[c]; v.y = acc[mt][nt].y + tb0[c + 1];
                *reinterpret_cast<float2*>(outp + (size_t)mtp * HID + c) = v;
            }
            if (mbt < M) {
                float2 v; v.x = acc[mt][nt].z + tb1[c]; v.y = acc[mt][nt].w + tb1[c + 1];
                *reinterpret_cast<float2*>(outp + (size_t)mbt * HID + c) = v;
            }
        }
    }
}

// ---------------- layer-1 aggregation + relu + head dot products ----------------
__global__ __launch_bounds__(256) void k_agg(const float* __restrict__ Whl,
                                             const float* __restrict__ Whr,
                                             int n) {
    const int warp = threadIdx.x >> 5, lane = threadIdx.x & 31;
    const int node = blockIdx.x * 8 + warp;
    if (node >= n) return;

    const int beg = g_off[node], end = g_off[node + 1];
    const int deg = end - beg;

    float4 a0 = make_float4(0.f, 0.f, 0.f, 0.f);
    float4 a1 = make_float4(0.f, 0.f, 0.f, 0.f);
    const float4* Z = reinterpret_cast<const float4*>(g_z);

    int e = beg;
    for (; e + 3 < end; e += 4) {
        int j0 = g_csr[e], j1 = g_csr[e + 1], j2 = g_csr[e + 2], j3 = g_csr[e + 3];
        const float4* p0 = Z + (size_t)j0 * 64;
        const float4* p1 = Z + (size_t)j1 * 64;
        const float4* p2 = Z + (size_t)j2 * 64;
        const float4* p3 = Z + (size_t)j3 * 64;
        float4 x0 = p0[lane], x1 = p1[lane], x2 = p2[lane], x3 = p3[lane];
        float4 y0 = p0[32 + lane], y1 = p1[32 + lane], y2 = p2[32 + lane], y3 = p3[32 + lane];
        a0.x += (x0.x + x1.x) + (x2.x + x3.x);
        a0.y += (x0.y + x1.y) + (x2.y + x3.y);
        a0.z += (x0.z + x1.z) + (x2.z + x3.z);
        a0.w += (x0.w + x1.w) + (x2.w + x3.w);
        a1.x += (y0.x + y1.x) + (y2.x + y3.x);
        a1.y += (y0.y + y1.y) + (y2.y + y3.y);
        a1.z += (y0.z + y1.z) + (y2.z + y3.z);
        a1.w += (y0.w + y1.w) + (y2.w + y3.w);
    }
    for (; e < end; e++) {
        int j0 = g_csr[e];
        const float4* p0 = Z + (size_t)j0 * 64;
        float4 x0 = p0[lane], y0 = p0[32 + lane];
        a0.x += x0.x; a0.y += x0.y; a0.z += x0.z; a0.w += x0.w;
        a1.x += y0.x; a1.y += y0.y; a1.z += y0.z; a1.w += y0.w;
    }

    const float inv = 1.0f / (float)max(deg, 1);
    const float4* R = reinterpret_cast<const float4*>(g_r);
    float4 r0 = R[(size_t)node * 64 + lane];
    float4 r1 = R[(size_t)node * 64 + 32 + lane];

    float4 h0, h1v;
    h0.x = fmaxf(a0.x * inv + r0.x, 0.f);
    h0.y = fmaxf(a0.y * inv + r0.y, 0.f);
    h0.z = fmaxf(a0.z * inv + r0.z, 0.f);
    h0.w = fmaxf(a0.w * inv + r0.w, 0.f);
    h1v.x = fmaxf(a1.x * inv + r1.x, 0.f);
    h1v.y = fmaxf(a1.y * inv + r1.y, 0.f);
    h1v.z = fmaxf(a1.z * inv + r1.z, 0.f);
    h1v.w = fmaxf(a1.w * inv + r1.w, 0.f);

    const float4* wl4 = reinterpret_cast<const float4*>(Whl);
    const float4* wr4 = reinterpret_cast<const float4*>(Whr);
    float4 wl0 = __ldg(&wl4[lane]), wl1 = __ldg(&wl4[32 + lane]);
    float4 wr0 = __ldg(&wr4[lane]), wr1 = __ldg(&wr4[32 + lane]);

    float sl = h0.x * wl0.x + h0.y * wl0.y + h0.z * wl0.z + h0.w * wl0.w
             + h1v.x * wl1.x + h1v.y * wl1.y + h1v.z * wl1.z + h1v.w * wl1.w;
    float sr = h0.x * wr0.x + h0.y * wr0.y + h0.z * wr0.z + h0.w * wr0.w
             + h1v.x * wr1.x + h1v.y * wr1.y + h1v.z * wr1.z + h1v.w * wr1.w;

    #pragma unroll
    for (int o = 16; o > 0; o >>= 1) {
        sl += __shfl_xor_sync(0xffffffffu, sl, o);
        sr += __shfl_xor_sync(0xffffffffu, sr, o);
    }
    if (lane == 0) { g_sl[node] = sl; g_sr[node] = sr; }
}

// ---------------- layer-2 scalar aggregation ----------------
__global__ void k_out(const float* __restrict__ bh, float* __restrict__ out, int n) {
    int node = blockIdx.x * blockDim.x + threadIdx.x;
    if (node >= n) return;
    int beg = g_off[node], end = g_off[node + 1];
    float s = 0.f;
    for (int e = beg; e < end; ++e) s += g_sl[g_csr[e]];
    out[node] = s / (float)max(end - beg, 1) + bh[0] + g_sr[node];
}

// ---------------- launch ----------------
extern "C" void kernel_launch(void* const* d_in, const int* in_sizes, int n_in,
                              void* d_out, int out_size) {
    const float* x    = (const float*)d_in[0];
    const int*   edge = (const int*)  d_in[1];
    const int*   ts   = (const int*)  d_in[2];
    const float* te   = (const float*)d_in[3];
    const float* W1l  = (const float*)d_in[4];
    const float* b1   = (const float*)d_in[5];
    const float* W1r  = (const float*)d_in[6];
    const float* Whl  = (const float*)d_in[7];
    const float* bh   = (const float*)d_in[8];
    const float* Whr  = (const float*)d_in[9];
    float* out = (float*)d_out;

    const int N = in_sizes[0] / INDIM;
    const int E = in_sizes[1] / 2;
    const int NB = (N + SCAN_B - 1) / SCAN_B;

    static int smem_set = 0;
    const int GEMM_SMEM = 4 * ASZ * sizeof(float);   // 73728 B
    if (!smem_set) {
        cudaFuncSetAttribute(k_gemm, cudaFuncAttributeMaxDynamicSharedMemorySize, GEMM_SMEM);
        smem_set = 1;
    }

    k_zero  <<<(N + 255) / 256, 256>>>(N);
    k_count <<<(E + 255) / 256, 256>>>(edge, E);
    k_scan1 <<<NB, SCAN_B>>>(N);
    k_scan2 <<<1, 128>>>(NB, N);
    k_scan3 <<<NB, SCAN_B>>>(N);
    k_fill  <<<(E + 255) / 256, 256>>>(edge, E);
    k_teproj<<<NUMT, HID>>>(te, W1l, W1r, b1);
    dim3 gg(512 / BN, (N + BM - 1) / BM);
    k_gemm  <<<gg, 256, GEMM_SMEM>>>(x, W1l, W1r, ts, N);
    k_agg   <<<(N + 7) / 8, 256>>>(Whl, Whr, N);
    k_out   <<<(N + 255) / 256, 256>>>(bh, out, N);
}

// round 3
// speedup vs baseline: 2.1105x; 1.0279x over previous
#include <cuda_runtime.h>
#include <cuda_bf16.h>
#include <cstdint>

#define NN      50000
#define EE      800000
#define INDIM   256
#define TD      16
#define HID     256
#define NUMT    50
#define AUG     (INDIM + TD)

// ---------------- scratch (device globals; no runtime alloc) ----------------
__device__ int   g_cnt[NN];
__device__ int   g_off[NN + 1];
__device__ int   g_cur[NN];
__device__ int   g_bsum[128];
__device__ int   g_bpre[128];
__device__ int   g_csr[EE];
__device__ float g_z[(size_t)NN * HID];   // x @ W1_l^T (+ time-l term)
__device__ float g_r[(size_t)NN * HID];   // x @ W1_r^T (+ time-r term + b1)
__device__ float g_teL[NUMT * HID];
__device__ float g_teR[NUMT * HID];
__device__ float g_psl[2][NN];
__device__ float g_psr[2][NN];

// ---------------- CSR build ----------------
__global__ void k_zero(int n) {
    int i = blockIdx.x * blockDim.x + threadIdx.x;
    if (i < n) g_cnt[i] = 0;
}

__global__ void k_count(const int* __restrict__ edge, int E) {
    int e = blockIdx.x * blockDim.x + threadIdx.x;
    if (e < E) atomicAdd(&g_cnt[edge[E + e]], 1);
}

#define SCAN_B 512
__global__ __launch_bounds__(SCAN_B) void k_scan1(int n) {
    __shared__ int ws[16];
    const int tid = threadIdx.x, lane = tid & 31, w = tid >> 5;
    const int idx = blockIdx.x * SCAN_B + tid;
    int v = (idx < n) ? g_cnt[idx] : 0;
    int sv = v;
    #pragma unroll
    for (int o = 1; o < 32; o <<= 1) {
        int t = __shfl_up_sync(0xffffffffu, sv, o);
        if (lane >= o) sv += t;
    }
    if (lane == 31) ws[w] = sv;
    __syncthreads();
    if (w == 0) {
        int t = (lane < 16) ? ws[lane] : 0;
        #pragma unroll
        for (int o = 1; o < 16; o <<= 1) {
            int u = __shfl_up_sync(0xffffffffu, t, o);
            if (lane >= o) t += u;
        }
        if (lane < 16) ws[lane] = t;
    }
    __syncthreads();
    int excl = (w ? ws[w - 1] : 0) + sv - v;
    if (idx < n) g_off[idx] = excl;
    if (tid == 0) g_bsum[blockIdx.x] = ws[15];
}

__global__ void k_scan2(int nb, int n) {
    __shared__ int wsum[5];
    const int tid = threadIdx.x, lane = tid & 31, w = tid >> 5;
    int v = (tid < nb) ? g_bsum[tid] : 0;
    int sv = v;
    #pragma unroll
    for (int o = 1; o < 32; o <<= 1) {
        int t = __shfl_up_sync(0xffffffffu, sv, o);
        if (lane >= o) sv += t;
    }
    if (lane == 31) wsum[w] = sv;
    __syncthreads();
    if (tid == 0) {
        int a = 0;
        #pragma unroll
        for (int i = 0; i < 4; i++) { int t = wsum[i]; wsum[i] = a; a += t; }
        wsum[4] = a;
    }
    __syncthreads();
    int excl = wsum[w] + sv - v;
    if (tid < nb) g_bpre[tid] = excl;
    if (tid == 0) g_off[n] = wsum[4];
}

__global__ __launch_bounds__(SCAN_B) void k_scan3(int n) {
    int idx = blockIdx.x * SCAN_B + threadIdx.x;
    if (idx < n) {
        int o = g_off[idx] + g_bpre[blockIdx.x];
        g_off[idx] = o;
        g_cur[idx] = o;
    }
}

__global__ void k_fill(const int* __restrict__ edge, int E) {
    int e = blockIdx.x * blockDim.x + threadIdx.x;
    if (e < E) {
        int s = edge[e];
        int d = edge[E + e];
        int p = atomicAdd(&g_cur[d], 1);
        g_csr[p] = s;
    }
}

// ---------------- time-embedding projection tables ----------------
__global__ void k_teproj(const float* __restrict__ te,
                         const float* __restrict__ W1l,
                         const float* __restrict__ W1r,
                         const float* __restrict__ b1) {
    int t = blockIdx.x;
    int h = threadIdx.x;
    float sl = 0.f, sr = 0.f;
    #pragma unroll
    for (int d = 0; d < TD; ++d) {
        float tv = te[t * TD + d];
        sl += tv * W1l[h * AUG + INDIM + d];
        sr += tv * W1r[h * AUG + INDIM + d];
    }
    g_teL[t * HID + h] = sl;
    g_teR[t * HID + h] = sr + b1[h];
}

// ---------------- tf32 tensor-core GEMM ----------------
#define BM 128
#define BN 128
#define BK 32
#define LDAS 36
#define ASZ (BM * LDAS)

__device__ __forceinline__ void cp16(float* dst, const float* src, bool valid) {
    uint32_t d = (uint32_t)__cvta_generic_to_shared(dst);
    int sz = valid ? 16 : 0;
    asm volatile("cp.async.cg.shared.global [%0], [%1], 16, %2;\n"
                 :: "r"(d), "l"(src), "r"(sz));
}

__device__ __forceinline__ void mma_tf32(float4& d, const uint32_t a[4], const uint32_t b[2]) {
    asm volatile(
        "mma.sync.aligned.m16n8k8.row.col.f32.tf32.tf32.f32 "
        "{%0,%1,%2,%3}, {%4,%5,%6,%7}, {%8,%9}, {%0,%1,%2,%3};\n"
        : "+f"(d.x), "+f"(d.y), "+f"(d.z), "+f"(d.w)
        : "r"(a[0]), "r"(a[1]), "r"(a[2]), "r"(a[3]), "r"(b[0]), "r"(b[1]));
}

__device__ __forceinline__ void load_tile(float* As, float* Bs,
                                          const float* __restrict__ X,
                                          const float* __restrict__ Wp,
                                          int m0, int cbase, int M, int kb, int tid) {
    #pragma unroll
    for (int i = 0; i < 4; i++) {
        int c = tid + 256 * i;
        int row = c >> 3, col = (c & 7) * 4;
        int m = m0 + row;
        bool va = m < M;
        const float* sa = X + (size_t)(va ? m : 0) * INDIM + kb + col;
        cp16(As + row * LDAS + col, sa, va);
        const float* sb = Wp + (size_t)(cbase + row) * AUG + kb + col;
        cp16(Bs + row * LDAS + col, sb, true);
    }
}

__global__ __launch_bounds__(256) void k_gemm(const float* __restrict__ X,
                                              const float* __restrict__ W1l,
                                              const float* __restrict__ W1r,
                                              const int* __restrict__ ts,
                                              int M) {
    extern __shared__ float sm[];
    float* As  = sm;
    float* Bsm = sm + 2 * ASZ;

    const int tid = threadIdx.x;
    const int n0 = blockIdx.x * BN;
    const int m0 = blockIdx.y * BM;
    const bool isZ = (n0 < 256);
    const float* Wp = isZ ? W1l : W1r;
    const int cbase = isZ ? n0 : (n0 - 256);

    const int warp = tid >> 5, lane = tid & 31;
    const int wm = warp >> 2, wn = warp & 3;
    const int g = lane >> 2, tig = lane & 3;

    float4 acc[4][4];
    #pragma unroll
    for (int i = 0; i < 4; i++)
        #pragma unroll
        for (int j = 0; j < 4; j++) acc[i][j] = make_float4(0.f, 0.f, 0.f, 0.f);

    load_tile(As, Bsm, X, Wp, m0, cbase, M, 0, tid);
    asm volatile("cp.async.commit_group;\n");
    load_tile(As + ASZ, Bsm + ASZ, X, Wp, m0, cbase, M, BK, tid);
    asm volatile("cp.async.commit_group;\n");
    asm volatile("cp.async.wait_group 1;\n");
    __syncthreads();

    #pragma unroll 1
    for (int ks = 0; ks < INDIM / BK; ks++) {
        const int buf = ks & 1;
        const float* Ab = As + buf * ASZ;
        const float* Bb = Bsm + buf * ASZ;

        #pragma unroll
        for (int kk = 0; kk < 4; kk++) {
            uint32_t af[4][4], bf[4][2];
            const float* Ap = Ab + (wm * 64 + g) * LDAS + kk * 8 + tig;
            #pragma unroll
            for (int mt = 0; mt < 4; mt++) {
                af[mt][0] = __float_as_uint(Ap[(mt * 16)     * LDAS]);
                af[mt][1] = __float_as_uint(Ap[(mt * 16 + 8) * LDAS]);
                af[mt][2] = __float_as_uint(Ap[(mt * 16)     * LDAS + 4]);
                af[mt][3] = __float_as_uint(Ap[(mt * 16 + 8) * LDAS + 4]);
            }
            const float* Bp = Bb + (wn * 32 + g) * LDAS + kk * 8 + tig;
            #pragma unroll
            for (int nt = 0; nt < 4; nt++) {
                bf[nt][0] = __float_as_uint(Bp[(nt * 8) * LDAS]);
                bf[nt][1] = __float_as_uint(Bp[(nt * 8) * LDAS + 4]);
            }
            #pragma unroll
            for (int mt = 0; mt < 4; mt++)
                #pragma unroll
                for (int nt = 0; nt < 4; nt++)
                    mma_tf32(acc[mt][nt], af[mt], bf[nt]);
        }
        __syncthreads();
        if (ks + 2 < INDIM / BK) {
            load_tile(As + buf * ASZ, Bsm + buf * ASZ, X, Wp, m0, cbase, M, (ks + 2) * BK, tid);
            asm volatile("cp.async.commit_group;\n");
            asm volatile("cp.async.wait_group 1;\n");
        } else {
            asm volatile("cp.async.wait_group 0;\n");
        }
        __syncthreads();
    }

    float* outp = isZ ? g_z : g_r;
    const float* tabB = isZ ? g_teL : g_teR;
    #pragma unroll
    for (int mt = 0; mt < 4; mt++) {
        int mtp = m0 + wm * 64 + mt * 16 + g;
        int mbt = mtp + 8;
        int t0 = (mtp < M) ? ts[mtp] : 0;
        int t1 = (mbt < M) ? ts[mbt] : 0;
        const float* tb0 = tabB + t0 * HID;
        const float* tb1 = tabB + t1 * HID;
        #pragma unroll
        for (int nt = 0; nt < 4; nt++) {
            int c = cbase + wn * 32 + nt * 8 + tig * 2;
            if (mtp < M) {
                float2 v; v.x = acc[mt][nt].x + tb0[c]; v.y = acc[mt][nt].y + tb0[c + 1];
                *reinterpret_cast<float2*>(outp + (size_t)mtp * HID + c) = v;
            }
            if (mbt < M) {
                float2 v; v.x = acc[mt][nt].z + tb1[c]; v.y = acc[mt][nt].w + tb1[c + 1];
                *reinterpret_cast<float2*>(outp + (size_t)mbt * HID + c) = v;
            }
        }
    }
}

// ---------------- layer-1 aggregation (half row per warp) ----------------
__global__ __launch_bounds__(256) void k_agg(const float* __restrict__ Whl,
                                             const float* __restrict__ Whr,
                                             int n) {
    const int gw = blockIdx.x * 8 + (threadIdx.x >> 5);
    const int lane = threadIdx.x & 31;
    const int node = gw >> 1, half = gw & 1;
    if (node >= n) return;

    const int beg = g_off[node], end = g_off[node + 1];
    const int deg = end - beg;
    const int off = half * 32 + lane;
    const float4* __restrict__ Z = reinterpret_cast<const float4*>(g_z);

    float4 a = make_float4(0.f, 0.f, 0.f, 0.f);
    int e = beg;
    for (; e + 7 < end; e += 8) {
        int j0 = g_csr[e],     j1 = g_csr[e + 1], j2 = g_csr[e + 2], j3 = g_csr[e + 3];
        int j4 = g_csr[e + 4], j5 = g_csr[e + 5], j6 = g_csr[e + 6], j7 = g_csr[e + 7];
        float4 v0 = Z[(size_t)j0 * 64 + off];
        float4 v1 = Z[(size_t)j1 * 64 + off];
        float4 v2 = Z[(size_t)j2 * 64 + off];
        float4 v3 = Z[(size_t)j3 * 64 + off];
        float4 v4 = Z[(size_t)j4 * 64 + off];
        float4 v5 = Z[(size_t)j5 * 64 + off];
        float4 v6 = Z[(size_t)j6 * 64 + off];
        float4 v7 = Z[(size_t)j7 * 64 + off];
        a.x += ((v0.x + v1.x) + (v2.x + v3.x)) + ((v4.x + v5.x) + (v6.x + v7.x));
        a.y += ((v0.y + v1.y) + (v2.y + v3.y)) + ((v4.y + v5.y) + (v6.y + v7.y));
        a.z += ((v0.z + v1.z) + (v2.z + v3.z)) + ((v4.z + v5.z) + (v6.z + v7.z));
        a.w += ((v0.w + v1.w) + (v2.w + v3.w)) + ((v4.w + v5.w) + (v6.w + v7.w));
    }
    for (; e + 1 < end; e += 2) {
        int j0 = g_csr[e], j1 = g_csr[e + 1];
        float4 v0 = Z[(size_t)j0 * 64 + off];
        float4 v1 = Z[(size_t)j1 * 64 + off];
        a.x += v0.x + v1.x; a.y += v0.y + v1.y;
        a.z += v0.z + v1.z; a.w += v0.w + v1.w;
    }
    if (e < end) {
        float4 v0 = Z[(size_t)g_csr[e] * 64 + off];
        a.x += v0.x; a.y += v0.y; a.z += v0.z; a.w += v0.w;
    }

    const float inv = 1.0f / (float)max(deg, 1);
    float4 r = reinterpret_cast<const float4*>(g_r)[(size_t)node * 64 + off];
    float4 h;
    h.x = fmaxf(fmaf(a.x, inv, r.x), 0.f);
    h.y = fmaxf(fmaf(a.y, inv, r.y), 0.f);
    h.z = fmaxf(fmaf(a.z, inv, r.z), 0.f);
    h.w = fmaxf(fmaf(a.w, inv, r.w), 0.f);

    float4 wl = __ldg(&reinterpret_cast<const float4*>(Whl)[off]);
    float4 wr = __ldg(&reinterpret_cast<const float4*>(Whr)[off]);
    float sl = h.x * wl.x + h.y * wl.y + h.z * wl.z + h.w * wl.w;
    float sr = h.x * wr.x + h.y * wr.y + h.z * wr.z + h.w * wr.w;

    #pragma unroll
    for (int o = 16; o > 0; o >>= 1) {
        sl += __shfl_xor_sync(0xffffffffu, sl, o);
        sr += __shfl_xor_sync(0xffffffffu, sr, o);
    }
    if (lane == 0) { g_psl[half][node] = sl; g_psr[half][node] = sr; }
}

// ---------------- layer-2 scalar aggregation ----------------
__global__ void k_out(const float* __restrict__ bh, float* __restrict__ out, int n) {
    int node = blockIdx.x * blockDim.x + threadIdx.x;
    if (node >= n) return;
    int beg = g_off[node], end = g_off[node + 1];
    float s = 0.f;
    int e = beg;
    for (; e + 3 < end; e += 4) {
        int j0 = g_csr[e], j1 = g_csr[e + 1], j2 = g_csr[e + 2], j3 = g_csr[e + 3];
        float s0 = g_psl[0][j0] + g_psl[1][j0];
        float s1 = g_psl[0][j1] + g_psl[1][j1];
        float s2 = g_psl[0][j2] + g_psl[1][j2];
        float s3 = g_psl[0][j3] + g_psl[1][j3];
        s += (s0 + s1) + (s2 + s3);
    }
    for (; e < end; ++e) { int j = g_csr[e]; s += g_psl[0][j] + g_psl[1][j]; }
    out[node] = s / (float)max(end - beg, 1) + bh[0] + g_psr[0][node] + g_psr[1][node];
}

// ---------------- launch ----------------
extern "C" void kernel_launch(void* const* d_in, const int* in_sizes, int n_in,
                              void* d_out, int out_size) {
    const float* x    = (const float*)d_in[0];
    const int*   edge = (const int*)  d_in[1];
    const int*   ts   = (const int*)  d_in[2];
    const float* te   = (const float*)d_in[3];
    const float* W1l  = (const float*)d_in[4];
    const float* b1   = (const float*)d_in[5];
    const float* W1r  = (const float*)d_in[6];
    const float* Whl  = (const float*)d_in[7];
    const float* bh   = (const float*)d_in[8];
    const float* Whr  = (const float*)d_in[9];
    float* out = (float*)d_out;

    const int N = in_sizes[0] / INDIM;
    const int E = in_sizes[1] / 2;
    const int NB = (N + SCAN_B - 1) / SCAN_B;

    static cudaStream_t s_side = nullptr;
    static cudaEvent_t ev_fork = nullptr, ev_join = nullptr;
    static int smem_set = 0;
    const int GEMM_SMEM = 4 * ASZ * sizeof(float);
    if (!smem_set) {
        cudaFuncSetAttribute(k_gemm, cudaFuncAttributeMaxDynamicSharedMemorySize, GEMM_SMEM);
        cudaStreamCreateWithFlags(&s_side, cudaStreamNonBlocking);
        cudaEventCreateWithFlags(&ev_fork, cudaEventDisableTiming);
        cudaEventCreateWithFlags(&ev_join, cudaEventDisableTiming);
        smem_set = 1;
    }

    // fork: CSR build on side stream, GEMM path on main stream
    cudaEventRecord(ev_fork, 0);
    cudaStreamWaitEvent(s_side, ev_fork, 0);

    k_zero  <<<(N + 255) / 256, 256, 0, s_side>>>(N);
    k_count <<<(E + 255) / 256, 256, 0, s_side>>>(edge, E);
    k_scan1 <<<NB, SCAN_B, 0, s_side>>>(N);
    k_scan2 <<<1, 128, 0, s_side>>>(NB, N);
    k_scan3 <<<NB, SCAN_B, 0, s_side>>>(N);
    k_fill  <<<(E + 255) / 256, 256, 0, s_side>>>(edge, E);

    k_teproj<<<NUMT, HID>>>(te, W1l, W1r, b1);
    dim3 gg(512 / BN, (N + BM - 1) / BM);
    k_gemm  <<<gg, 256, GEMM_SMEM>>>(x, W1l, W1r, ts, N);

    // join
    cudaEventRecord(ev_join, s_side);
    cudaStreamWaitEvent(0, ev_join, 0);

    k_agg   <<<(2 * N + 7) / 8, 256>>>(Whl, Whr, N);
    k_out   <<<(N + 255) / 256, 256>>>(bh, out, N);
}

// round 4
// speedup vs baseline: 2.3751x; 1.1254x over previous
#include <cuda_runtime.h>
#include <cuda_bf16.h>
#include <cstdint>

#define NN      50000
#define EE      800000
#define INDIM   256
#define TD      16
#define HID     256
#define NUMT    50
#define AUG     (INDIM + TD)

// ---------------- scratch (device globals; no runtime alloc) ----------------
__device__ int   g_cnt[NN];
__device__ int   g_off[NN + 1];
__device__ int   g_cur[NN];
__device__ int   g_bsum[128];
__device__ int   g_bpre[128];
__device__ int   g_csr[EE];
__device__ __nv_bfloat16 g_zh[(size_t)NN * HID];  // bf16 z = x@W1_l^T + time-l
__device__ float g_r[(size_t)NN * HID];           // fp32 r = x@W1_r^T + time-r + b1
__device__ float g_teL[NUMT * HID];
__device__ float g_teR[NUMT * HID];
__device__ float g_sl[NN];
__device__ float g_sr[NN];

// ---------------- CSR build ----------------
__global__ void k_zero(int n) {
    int i = blockIdx.x * blockDim.x + threadIdx.x;
    if (i < n) g_cnt[i] = 0;
}

__global__ void k_count(const int* __restrict__ edge, int E) {
    int e = blockIdx.x * blockDim.x + threadIdx.x;
    if (e < E) atomicAdd(&g_cnt[edge[E + e]], 1);
}

#define SCAN_B 512
__global__ __launch_bounds__(SCAN_B) void k_scan1(int n) {
    __shared__ int ws[16];
    const int tid = threadIdx.x, lane = tid & 31, w = tid >> 5;
    const int idx = blockIdx.x * SCAN_B + tid;
    int v = (idx < n) ? g_cnt[idx] : 0;
    int sv = v;
    #pragma unroll
    for (int o = 1; o < 32; o <<= 1) {
        int t = __shfl_up_sync(0xffffffffu, sv, o);
        if (lane >= o) sv += t;
    }
    if (lane == 31) ws[w] = sv;
    __syncthreads();
    if (w == 0) {
        int t = (lane < 16) ? ws[lane] : 0;
        #pragma unroll
        for (int o = 1; o < 16; o <<= 1) {
            int u = __shfl_up_sync(0xffffffffu, t, o);
            if (lane >= o) t += u;
        }
        if (lane < 16) ws[lane] = t;
    }
    __syncthreads();
    int excl = (w ? ws[w - 1] : 0) + sv - v;
    if (idx < n) g_off[idx] = excl;
    if (tid == 0) g_bsum[blockIdx.x] = ws[15];
}

__global__ void k_scan2(int nb, int n) {
    __shared__ int wsum[5];
    const int tid = threadIdx.x, lane = tid & 31, w = tid >> 5;
    int v = (tid < nb) ? g_bsum[tid] : 0;
    int sv = v;
    #pragma unroll
    for (int o = 1; o < 32; o <<= 1) {
        int t = __shfl_up_sync(0xffffffffu, sv, o);
        if (lane >= o) sv += t;
    }
    if (lane == 31) wsum[w] = sv;
    __syncthreads();
    if (tid == 0) {
        int a = 0;
        #pragma unroll
        for (int i = 0; i < 4; i++) { int t = wsum[i]; wsum[i] = a; a += t; }
        wsum[4] = a;
    }
    __syncthreads();
    int excl = wsum[w] + sv - v;
    if (tid < nb) g_bpre[tid] = excl;
    if (tid == 0) g_off[n] = wsum[4];
}

__global__ __launch_bounds__(SCAN_B) void k_scan3(int n) {
    int idx = blockIdx.x * SCAN_B + threadIdx.x;
    if (idx < n) {
        int o = g_off[idx] + g_bpre[blockIdx.x];
        g_off[idx] = o;
        g_cur[idx] = o;
    }
}

__global__ void k_fill(const int* __restrict__ edge, int E) {
    int e = blockIdx.x * blockDim.x + threadIdx.x;
    if (e < E) {
        int s = edge[e];
        int d = edge[E + e];
        int p = atomicAdd(&g_cur[d], 1);
        g_csr[p] = s;
    }
}

// ---------------- time-embedding projection tables ----------------
__global__ void k_teproj(const float* __restrict__ te,
                         const float* __restrict__ W1l,
                         const float* __restrict__ W1r,
                         const float* __restrict__ b1) {
    int t = blockIdx.x;
    int h = threadIdx.x;
    float sl = 0.f, sr = 0.f;
    #pragma unroll
    for (int d = 0; d < TD; ++d) {
        float tv = te[t * TD + d];
        sl += tv * W1l[h * AUG + INDIM + d];
        sr += tv * W1r[h * AUG + INDIM + d];
    }
    g_teL[t * HID + h] = sl;
    g_teR[t * HID + h] = sr + b1[h];
}

// ---------------- tf32 tensor-core GEMM ----------------
#define BM 128
#define BN 128
#define BK 32
#define LDAS 36
#define ASZ (BM * LDAS)

__device__ __forceinline__ void cp16(float* dst, const float* src, bool valid) {
    uint32_t d = (uint32_t)__cvta_generic_to_shared(dst);
    int sz = valid ? 16 : 0;
    asm volatile("cp.async.cg.shared.global [%0], [%1], 16, %2;\n"
                 :: "r"(d), "l"(src), "r"(sz));
}

__device__ __forceinline__ void mma_tf32(float4& d, const uint32_t a[4], const uint32_t b[2]) {
    asm volatile(
        "mma.sync.aligned.m16n8k8.row.col.f32.tf32.tf32.f32 "
        "{%0,%1,%2,%3}, {%4,%5,%6,%7}, {%8,%9}, {%0,%1,%2,%3};\n"
        : "+f"(d.x), "+f"(d.y), "+f"(d.z), "+f"(d.w)
        : "r"(a[0]), "r"(a[1]), "r"(a[2]), "r"(a[3]), "r"(b[0]), "r"(b[1]));
}

__device__ __forceinline__ void load_tile(float* As, float* Bs,
                                          const float* __restrict__ X,
                                          const float* __restrict__ Wp,
                                          int m0, int cbase, int M, int kb, int tid) {
    #pragma unroll
    for (int i = 0; i < 4; i++) {
        int c = tid + 256 * i;
        int row = c >> 3, col = (c & 7) * 4;
        int m = m0 + row;
        bool va = m < M;
        const float* sa = X + (size_t)(va ? m : 0) * INDIM + kb + col;
        cp16(As + row * LDAS + col, sa, va);
        const float* sb = Wp + (size_t)(cbase + row) * AUG + kb + col;
        cp16(Bs + row * LDAS + col, sb, true);
    }
}

__global__ __launch_bounds__(256) void k_gemm(const float* __restrict__ X,
                                              const float* __restrict__ W1l,
                                              const float* __restrict__ W1r,
                                              const int* __restrict__ ts,
                                              int M) {
    extern __shared__ float sm[];
    float* As  = sm;
    float* Bsm = sm + 2 * ASZ;

    const int tid = threadIdx.x;
    const int n0 = blockIdx.x * BN;
    const int m0 = blockIdx.y * BM;
    const bool isZ = (n0 < 256);
    const float* Wp = isZ ? W1l : W1r;
    const int cbase = isZ ? n0 : (n0 - 256);

    const int warp = tid >> 5, lane = tid & 31;
    const int wm = warp >> 2, wn = warp & 3;
    const int g = lane >> 2, tig = lane & 3;

    float4 acc[4][4];
    #pragma unroll
    for (int i = 0; i < 4; i++)
        #pragma unroll
        for (int j = 0; j < 4; j++) acc[i][j] = make_float4(0.f, 0.f, 0.f, 0.f);

    load_tile(As, Bsm, X, Wp, m0, cbase, M, 0, tid);
    asm volatile("cp.async.commit_group;\n");
    load_tile(As + ASZ, Bsm + ASZ, X, Wp, m0, cbase, M, BK, tid);
    asm volatile("cp.async.commit_group;\n");
    asm volatile("cp.async.wait_group 1;\n");
    __syncthreads();

    #pragma unroll 1
    for (int ks = 0; ks < INDIM / BK; ks++) {
        const int buf = ks & 1;
        const float* Ab = As + buf * ASZ;
        const float* Bb = Bsm + buf * ASZ;

        #pragma unroll
        for (int kk = 0; kk < 4; kk++) {
            uint32_t af[4][4], bf[4][2];
            const float* Ap = Ab + (wm * 64 + g) * LDAS + kk * 8 + tig;
            #pragma unroll
            for (int mt = 0; mt < 4; mt++) {
                af[mt][0] = __float_as_uint(Ap[(mt * 16)     * LDAS]);
                af[mt][1] = __float_as_uint(Ap[(mt * 16 + 8) * LDAS]);
                af[mt][2] = __float_as_uint(Ap[(mt * 16)     * LDAS + 4]);
                af[mt][3] = __float_as_uint(Ap[(mt * 16 + 8) * LDAS + 4]);
            }
            const float* Bp = Bb + (wn * 32 + g) * LDAS + kk * 8 + tig;
            #pragma unroll
            for (int nt = 0; nt < 4; nt++) {
                bf[nt][0] = __float_as_uint(Bp[(nt * 8) * LDAS]);
                bf[nt][1] = __float_as_uint(Bp[(nt * 8) * LDAS + 4]);
            }
            #pragma unroll
            for (int mt = 0; mt < 4; mt++)
                #pragma unroll
                for (int nt = 0; nt < 4; nt++)
                    mma_tf32(acc[mt][nt], af[mt], bf[nt]);
        }
        __syncthreads();
        if (ks + 2 < INDIM / BK) {
            load_tile(As + buf * ASZ, Bsm + buf * ASZ, X, Wp, m0, cbase, M, (ks + 2) * BK, tid);
            asm volatile("cp.async.commit_group;\n");
            asm volatile("cp.async.wait_group 1;\n");
        } else {
            asm volatile("cp.async.wait_group 0;\n");
        }
        __syncthreads();
    }

    // epilogue: add time tables; z -> bf16, r -> fp32
    const float* tabB = isZ ? g_teL : g_teR;
    #pragma unroll
    for (int mt = 0; mt < 4; mt++) {
        int mtp = m0 + wm * 64 + mt * 16 + g;
        int mbt = mtp + 8;
        int t0 = (mtp < M) ? ts[mtp] : 0;
        int t1 = (mbt < M) ? ts[mbt] : 0;
        const float* tb0 = tabB + t0 * HID;
        const float* tb1 = tabB + t1 * HID;
        #pragma unroll
        for (int nt = 0; nt < 4; nt++) {
            int c = cbase + wn * 32 + nt * 8 + tig * 2;
            if (isZ) {
                if (mtp < M) {
                    __nv_bfloat162 v = __floats2bfloat162_rn(acc[mt][nt].x + tb0[c],
                                                             acc[mt][nt].y + tb0[c + 1]);
                    *reinterpret_cast<__nv_bfloat162*>(g_zh + (size_t)mtp * HID + c) = v;
                }
                if (mbt < M) {
                    __nv_bfloat162 v = __floats2bfloat162_rn(acc[mt][nt].z + tb1[c],
                                                             acc[mt][nt].w + tb1[c + 1]);
                    *reinterpret_cast<__nv_bfloat162*>(g_zh + (size_t)mbt * HID + c) = v;
                }
            } else {
                if (mtp < M) {
                    float2 v; v.x = acc[mt][nt].x + tb0[c]; v.y = acc[mt][nt].y + tb0[c + 1];
                    *reinterpret_cast<float2*>(g_r + (size_t)mtp * HID + c) = v;
                }
                if (mbt < M) {
                    float2 v; v.x = acc[mt][nt].z + tb1[c]; v.y = acc[mt][nt].w + tb1[c + 1];
                    *reinterpret_cast<float2*>(g_r + (size_t)mbt * HID + c) = v;
                }
            }
        }
    }
}

// ---------------- layer-1 aggregation (bf16 z, node per warp) ----------------
// each lane owns dims [8*lane, 8*lane+8): one uint4 (8 bf16) per edge
__global__ __launch_bounds__(256) void k_agg(const float* __restrict__ Whl,
                                             const float* __restrict__ Whr,
                                             int n) {
    const int warp = threadIdx.x >> 5, lane = threadIdx.x & 31;
    const int node = blockIdx.x * 8 + warp;
    if (node >= n) return;

    const int beg = g_off[node], end = g_off[node + 1];
    const int deg = end - beg;
    const uint4* __restrict__ Z = reinterpret_cast<const uint4*>(g_zh);

    float a[8];
    #pragma unroll
    for (int i = 0; i < 8; i++) a[i] = 0.f;

    int e = beg;
    for (; e + 7 < end; e += 8) {
        uint4 v[8];
        #pragma unroll
        for (int q = 0; q < 8; q++)
            v[q] = Z[(size_t)g_csr[e + q] * 32 + lane];
        #pragma unroll
        for (int q = 0; q < 8; q++) {
            float2 p0 = __bfloat1622float2(*reinterpret_cast<__nv_bfloat162*>(&v[q].x));
            float2 p1 = __bfloat1622float2(*reinterpret_cast<__nv_bfloat162*>(&v[q].y));
            float2 p2 = __bfloat1622float2(*reinterpret_cast<__nv_bfloat162*>(&v[q].z));
            float2 p3 = __bfloat1622float2(*reinterpret_cast<__nv_bfloat162*>(&v[q].w));
            a[0] += p0.x; a[1] += p0.y; a[2] += p1.x; a[3] += p1.y;
            a[4] += p2.x; a[5] += p2.y; a[6] += p3.x; a[7] += p3.y;
        }
    }
    for (; e < end; e++) {
        uint4 v = Z[(size_t)g_csr[e] * 32 + lane];
        float2 p0 = __bfloat1622float2(*reinterpret_cast<__nv_bfloat162*>(&v.x));
        float2 p1 = __bfloat1622float2(*reinterpret_cast<__nv_bfloat162*>(&v.y));
        float2 p2 = __bfloat1622float2(*reinterpret_cast<__nv_bfloat162*>(&v.z));
        float2 p3 = __bfloat1622float2(*reinterpret_cast<__nv_bfloat162*>(&v.w));
        a[0] += p0.x; a[1] += p0.y; a[2] += p1.x; a[3] += p1.y;
        a[4] += p2.x; a[5] += p2.y; a[6] += p3.x; a[7] += p3.y;
    }

    const float inv = 1.0f / (float)max(deg, 1);
    const float4* R4 = reinterpret_cast<const float4*>(g_r) + (size_t)node * 64;
    float4 r0 = R4[2 * lane], r1 = R4[2 * lane + 1];
    float h[8];
    h[0] = fmaxf(fmaf(a[0], inv, r0.x), 0.f);
    h[1] = fmaxf(fmaf(a[1], inv, r0.y), 0.f);
    h[2] = fmaxf(fmaf(a[2], inv, r0.z), 0.f);
    h[3] = fmaxf(fmaf(a[3], inv, r0.w), 0.f);
    h[4] = fmaxf(fmaf(a[4], inv, r1.x), 0.f);
    h[5] = fmaxf(fmaf(a[5], inv, r1.y), 0.f);
    h[6] = fmaxf(fmaf(a[6], inv, r1.z), 0.f);
    h[7] = fmaxf(fmaf(a[7], inv, r1.w), 0.f);

    const float4* WL = reinterpret_cast<const float4*>(Whl);
    const float4* WR = reinterpret_cast<const float4*>(Whr);
    float4 wl0 = __ldg(&WL[2 * lane]), wl1 = __ldg(&WL[2 * lane + 1]);
    float4 wr0 = __ldg(&WR[2 * lane]), wr1 = __ldg(&WR[2 * lane + 1]);

    float sl = h[0] * wl0.x + h[1] * wl0.y + h[2] * wl0.z + h[3] * wl0.w
             + h[4] * wl1.x + h[5] * wl1.y + h[6] * wl1.z + h[7] * wl1.w;
    float sr = h[0] * wr0.x + h[1] * wr0.y + h[2] * wr0.z + h[3] * wr0.w
             + h[4] * wr1.x + h[5] * wr1.y + h[6] * wr1.z + h[7] * wr1.w;

    #pragma unroll
    for (int o = 16; o > 0; o >>= 1) {
        sl += __shfl_xor_sync(0xffffffffu, sl, o);
        sr += __shfl_xor_sync(0xffffffffu, sr, o);
    }
    if (lane == 0) { g_sl[node] = sl; g_sr[node] = sr; }
}

// ---------------- layer-2 scalar aggregation ----------------
__global__ void k_out(const float* __restrict__ bh, float* __restrict__ out, int n) {
    int node = blockIdx.x * blockDim.x + threadIdx.x;
    if (node >= n) return;
    int beg = g_off[node], end = g_off[node + 1];
    float s = 0.f;
    int e = beg;
    for (; e + 3 < end; e += 4) {
        float s0 = g_sl[g_csr[e]];
        float s1 = g_sl[g_csr[e + 1]];
        float s2 = g_sl[g_csr[e + 2]];
        float s3 = g_sl[g_csr[e + 3]];
        s += (s0 + s1) + (s2 + s3);
    }
    for (; e < end; ++e) s += g_sl[g_csr[e]];
    out[node] = s / (float)max(end - beg, 1) + bh[0] + g_sr[node];
}

// ---------------- launch ----------------
extern "C" void kernel_launch(void* const* d_in, const int* in_sizes, int n_in,
                              void* d_out, int out_size) {
    const float* x    = (const float*)d_in[0];
    const int*   edge = (const int*)  d_in[1];
    const int*   ts   = (const int*)  d_in[2];
    const float* te   = (const float*)d_in[3];
    const float* W1l  = (const float*)d_in[4];
    const float* b1   = (const float*)d_in[5];
    const float* W1r  = (const float*)d_in[6];
    const float* Whl  = (const float*)d_in[7];
    const float* bh   = (const float*)d_in[8];
    const float* Whr  = (const float*)d_in[9];
    float* out = (float*)d_out;

    const int N = in_sizes[0] / INDIM;
    const int E = in_sizes[1] / 2;
    const int NB = (N + SCAN_B - 1) / SCAN_B;

    static cudaStream_t s_side = nullptr;
    static cudaEvent_t ev_fork = nullptr, ev_join = nullptr;
    static int smem_set = 0;
    const int GEMM_SMEM = 4 * ASZ * sizeof(float);
    if (!smem_set) {
        cudaFuncSetAttribute(k_gemm, cudaFuncAttributeMaxDynamicSharedMemorySize, GEMM_SMEM);
        cudaStreamCreateWithFlags(&s_side, cudaStreamNonBlocking);
        cudaEventCreateWithFlags(&ev_fork, cudaEventDisableTiming);
        cudaEventCreateWithFlags(&ev_join, cudaEventDisableTiming);
        smem_set = 1;
    }

    cudaEventRecord(ev_fork, 0);
    cudaStreamWaitEvent(s_side, ev_fork, 0);

    k_zero  <<<(N + 255) / 256, 256, 0, s_side>>>(N);
    k_count <<<(E + 255) / 256, 256, 0, s_side>>>(edge, E);
    k_scan1 <<<NB, SCAN_B, 0, s_side>>>(N);
    k_scan2 <<<1, 128, 0, s_side>>>(NB, N);
    k_scan3 <<<NB, SCAN_B, 0, s_side>>>(N);
    k_fill  <<<(E + 255) / 256, 256, 0, s_side>>>(edge, E);

    k_teproj<<<NUMT, HID>>>(te, W1l, W1r, b1);
    dim3 gg(512 / BN, (N + BM - 1) / BM);
    k_gemm  <<<gg, 256, GEMM_SMEM>>>(x, W1l, W1r, ts, N);

    cudaEventRecord(ev_join, s_side);
    cudaStreamWaitEvent(0, ev_join, 0);

    k_agg   <<<(N + 7) / 8, 256>>>(Whl, Whr, N);
    k_out   <<<(N + 255) / 256, 256>>>(bh, out, N);
}